// round 9
// baseline (speedup 1.0000x reference)
#include <cuda_runtime.h>
#include <cuda_fp16.h>
#include <cstdint>
#include <math_constants.h>

#define Ls 1024
#define Bb 4
#define Es 1024
#define Hs 16
#define LB (Ls*Bb)        // 4096
#define BH (Bb*Hs)        // 64
#define LL (Ls*Ls)        // 1048576

// Scratch (device globals — allocation-free)
__device__ float g_q[LB*Es];
__device__ float g_k[LB*Es];
__device__ float g_v[LB*Es];
__device__ float g_ctx[LB*Es];
__device__ __half g_w[(size_t)BH*LL];      // 128 MB unnormalized weights u=exp(s-m_used)
__device__ float g_mt[BH*8*Ls];            // m_used per (bh, j-tile, row)
__device__ float g_fac[BH*8*Ls];           // exp(m_used - m_fin) * invZ
__device__ float2 g_stats[BH*Ls];          // per-row (m_fin, 1/Z)

// ---------------------------------------------------------------------------
// helpers
// ---------------------------------------------------------------------------
__device__ __forceinline__ float tf32r(float x) {
    uint32_t u;
    asm("cvt.rna.tf32.f32 %0, %1;" : "=r"(u) : "f"(x));
    return __uint_as_float(u);
}

__device__ __forceinline__ void mma_tf32(float c[4], const uint32_t a[4], const uint32_t b[2]) {
    asm volatile(
        "mma.sync.aligned.m16n8k8.row.col.f32.tf32.tf32.f32 "
        "{%0,%1,%2,%3}, {%4,%5,%6,%7}, {%8,%9}, {%0,%1,%2,%3};\n"
        : "+f"(c[0]), "+f"(c[1]), "+f"(c[2]), "+f"(c[3])
        : "r"(a[0]), "r"(a[1]), "r"(a[2]), "r"(a[3]), "r"(b[0]), "r"(b[1]));
}

__device__ __forceinline__ void mma_f16(float c[4], const uint32_t a[4], const uint32_t b[2]) {
    asm volatile(
        "mma.sync.aligned.m16n8k16.row.col.f32.f16.f16.f32 "
        "{%0,%1,%2,%3}, {%4,%5,%6,%7}, {%8,%9}, {%0,%1,%2,%3};\n"
        : "+f"(c[0]), "+f"(c[1]), "+f"(c[2]), "+f"(c[3])
        : "r"(a[0]), "r"(a[1]), "r"(a[2]), "r"(a[3]), "r"(b[0]), "r"(b[1]));
}

// ---------------------------------------------------------------------------
// NT GEMM (tensor core): C[4096,1024] = A[4096,1024] @ W[1024,1024]^T + bias
// ---------------------------------------------------------------------------
__global__ __launch_bounds__(256, 2) void gemm_nt_tc(
    const float* __restrict__ A, const float* __restrict__ W,
    const float* __restrict__ bias, float* __restrict__ C)
{
    const int K = 1024, N = 1024;
    __shared__ float As[128][36];
    __shared__ float Bs[128][36];
    const int tid = threadIdx.x;
    const int lane = tid & 31, wid = tid >> 5;
    const int g = lane >> 2, t4 = lane & 3;
    const int wm = wid >> 2, wn = wid & 3;           // 2 x 4 warps
    const int row0 = blockIdx.y * 128, col0 = blockIdx.x * 128;

    float c[4][4][4] = {};

    const int lr = tid >> 3;
    const int lc = (tid & 7) * 4;

    for (int kb = 0; kb < K; kb += 32) {
        #pragma unroll
        for (int it = 0; it < 4; it++) {
            int r = lr + it * 32;
            float4 va = *(const float4*)&A[(size_t)(row0 + r) * K + kb + lc];
            As[r][lc + 0] = tf32r(va.x); As[r][lc + 1] = tf32r(va.y);
            As[r][lc + 2] = tf32r(va.z); As[r][lc + 3] = tf32r(va.w);
            float4 vb = *(const float4*)&W[(size_t)(col0 + r) * K + kb + lc];
            Bs[r][lc + 0] = tf32r(vb.x); Bs[r][lc + 1] = tf32r(vb.y);
            Bs[r][lc + 2] = tf32r(vb.z); Bs[r][lc + 3] = tf32r(vb.w);
        }
        __syncthreads();
        #pragma unroll
        for (int ks = 0; ks < 32; ks += 8) {
            uint32_t a[4][4], b[4][2];
            #pragma unroll
            for (int i = 0; i < 4; i++) {
                int m = wm * 64 + i * 16;
                a[i][0] = __float_as_uint(As[m + g][ks + t4]);
                a[i][1] = __float_as_uint(As[m + g + 8][ks + t4]);
                a[i][2] = __float_as_uint(As[m + g][ks + t4 + 4]);
                a[i][3] = __float_as_uint(As[m + g + 8][ks + t4 + 4]);
            }
            #pragma unroll
            for (int j = 0; j < 4; j++) {
                int n = wn * 32 + j * 8;
                b[j][0] = __float_as_uint(Bs[n + g][ks + t4]);
                b[j][1] = __float_as_uint(Bs[n + g][ks + t4 + 4]);
            }
            #pragma unroll
            for (int i = 0; i < 4; i++)
                #pragma unroll
                for (int j = 0; j < 4; j++)
                    mma_tf32(c[i][j], a[i], b[j]);
        }
        __syncthreads();
    }

    #pragma unroll
    for (int i = 0; i < 4; i++) {
        int r = row0 + wm * 64 + i * 16 + g;
        #pragma unroll
        for (int j = 0; j < 4; j++) {
            int cc = col0 + wn * 32 + j * 8 + 2 * t4;
            float2 bv = *(const float2*)&bias[cc];
            float2 v0 = { c[i][j][0] + bv.x, c[i][j][1] + bv.y };
            float2 v1 = { c[i][j][2] + bv.x, c[i][j][3] + bv.y };
            *(float2*)&C[(size_t)r * N + cc] = v0;
            *(float2*)&C[(size_t)(r + 8) * N + cc] = v1;
        }
    }
}

// ---------------------------------------------------------------------------
// flash_attn: per (bh, 128-row i-tile), single sweep over 8 j-tiles.
// QK (tf32 MMA) -> mask+scale -> online softmax stats -> u=exp(s-m_new)
// stored fp16 to g_w + staged to SMEM -> PV (fp16 MMA) with ctx rescale.
// Dynamic SMEM (bytes):
//   Qs f[128][68] @0, Ks f[128][68] @34816, Ws h2[128][68] @69632,
//   Vt h2[64][68] @104448, pm[4][128] @121856, pz @123904,
//   rm @125952, rz @126464, fr @126976, mnew @127488  (total 128000)
// ---------------------------------------------------------------------------
#define FL_SMEM 128000
__global__ __launch_bounds__(256, 1) void flash_attn(const float* __restrict__ mask)
{
    extern __shared__ char smraw[];
    float*    Qs  = (float*)smraw;
    float*    Ks  = (float*)(smraw + 34816);
    __half2*  Ws2 = (__half2*)(smraw + 69632);
    __half*   Vh  = (__half*)(smraw + 104448);
    __half2*  Vt2 = (__half2*)(smraw + 104448);
    float*    pm  = (float*)(smraw + 121856);
    float*    pz  = (float*)(smraw + 123904);
    float*    rm  = (float*)(smraw + 125952);
    float*    rz  = (float*)(smraw + 126464);
    float*    fr  = (float*)(smraw + 126976);
    float*    mnw = (float*)(smraw + 127488);

    const int bh = blockIdx.y;
    const int b = bh >> 4, h = bh & 15;
    const int i0 = blockIdx.x * 128;
    const int tid = threadIdx.x;
    const int lane = tid & 31, wid = tid >> 5;
    const int g = lane >> 2, t4 = lane & 3;
    const int wm = wid >> 2, wn = wid & 3;          // 2 x 4 warps

    if (tid < 128) { rm[tid] = -CUDART_INF_F; rz[tid] = 0.f; }

    // Q tile [128 x 64] once (tf32-rounded)
    #pragma unroll
    for (int it = 0; it < 8; it++) {
        int idx = tid + it * 256;
        int r = idx >> 4, cc = (idx & 15) * 4;
        float4 v = *(const float4*)&g_q[((size_t)(i0 + r) * Bb + b) * Es + h * 64 + cc];
        Qs[r * 68 + cc + 0] = tf32r(v.x); Qs[r * 68 + cc + 1] = tf32r(v.y);
        Qs[r * 68 + cc + 2] = tf32r(v.z); Qs[r * 68 + cc + 3] = tf32r(v.w);
    }
    __syncthreads();

    float ctx[4][2][4] = {};
    const float* Mp = mask + (size_t)b * LL;

    for (int t = 0; t < 8; t++) {
        const int j0 = t * 128;

        // K tile [128 x 64]
        #pragma unroll
        for (int it = 0; it < 8; it++) {
            int idx = tid + it * 256;
            int r = idx >> 4, cc = (idx & 15) * 4;
            float4 v = *(const float4*)&g_k[((size_t)(j0 + r) * Bb + b) * Es + h * 64 + cc];
            Ks[r * 68 + cc + 0] = tf32r(v.x); Ks[r * 68 + cc + 1] = tf32r(v.y);
            Ks[r * 68 + cc + 2] = tf32r(v.z); Ks[r * 68 + cc + 3] = tf32r(v.w);
        }
        __syncthreads();

        // QK MMA -> c
        float c[4][4][4] = {};
        #pragma unroll
        for (int ks = 0; ks < 64; ks += 8) {
            uint32_t a[4][4], b2[4][2];
            #pragma unroll
            for (int i = 0; i < 4; i++) {
                int m = wm * 64 + i * 16;
                a[i][0] = __float_as_uint(Qs[(m + g) * 68 + ks + t4]);
                a[i][1] = __float_as_uint(Qs[(m + g + 8) * 68 + ks + t4]);
                a[i][2] = __float_as_uint(Qs[(m + g) * 68 + ks + t4 + 4]);
                a[i][3] = __float_as_uint(Qs[(m + g + 8) * 68 + ks + t4 + 4]);
            }
            #pragma unroll
            for (int j = 0; j < 4; j++) {
                int n = wn * 32 + j * 8;
                b2[j][0] = __float_as_uint(Ks[(n + g) * 68 + ks + t4]);
                b2[j][1] = __float_as_uint(Ks[(n + g) * 68 + ks + t4 + 4]);
            }
            #pragma unroll
            for (int i = 0; i < 4; i++)
                #pragma unroll
                for (int j = 0; j < 4; j++)
                    mma_tf32(c[i][j], a[i], b2[j]);
        }

        // mask + scale
        #pragma unroll
        for (int i = 0; i < 4; i++) {
            int r = i0 + wm * 64 + i * 16 + g;
            #pragma unroll
            for (int j = 0; j < 4; j++) {
                int cc = j0 + wn * 32 + j * 8 + 2 * t4;
                float2 m0 = *(const float2*)&Mp[(size_t)r * Ls + cc];
                float2 m1 = *(const float2*)&Mp[(size_t)(r + 8) * Ls + cc];
                c[i][j][0] = c[i][j][0] * 0.125f + m0.x;
                c[i][j][1] = c[i][j][1] * 0.125f + m0.y;
                c[i][j][2] = c[i][j][2] * 0.125f + m1.x;
                c[i][j][3] = c[i][j][3] * 0.125f + m1.y;
            }
        }

        // tile-local stats per row -> pm/pz
        #pragma unroll
        for (int i = 0; i < 4; i++) {
            #pragma unroll
            for (int sub = 0; sub < 2; sub++) {
                float tm = c[i][0][2 * sub];
                #pragma unroll
                for (int j = 0; j < 4; j++) {
                    tm = fmaxf(tm, c[i][j][2 * sub + 0]);
                    tm = fmaxf(tm, c[i][j][2 * sub + 1]);
                }
                float ts = 0.f;
                #pragma unroll
                for (int j = 0; j < 4; j++) {
                    ts += __expf(c[i][j][2 * sub + 0] - tm);
                    ts += __expf(c[i][j][2 * sub + 1] - tm);
                }
                #pragma unroll
                for (int o = 1; o < 4; o <<= 1) {
                    float om = __shfl_xor_sync(0xffffffffu, tm, o);
                    float os = __shfl_xor_sync(0xffffffffu, ts, o);
                    float nm = fmaxf(tm, om);
                    ts = ts * __expf(tm - nm) + os * __expf(om - nm);
                    tm = nm;
                }
                if (t4 == 0) {
                    int rr = wm * 64 + i * 16 + g + 8 * sub;
                    pm[wn * 128 + rr] = tm;
                    pz[wn * 128 + rr] = ts;
                }
            }
        }
        __syncthreads();

        // merge across warps + online update
        if (tid < 128) {
            float tmax = pm[tid];
            #pragma unroll
            for (int w = 1; w < 4; w++) tmax = fmaxf(tmax, pm[w * 128 + tid]);
            float tz = 0.f;
            #pragma unroll
            for (int w = 0; w < 4; w++)
                tz += pz[w * 128 + tid] * __expf(pm[w * 128 + tid] - tmax);
            float mo = rm[tid];
            float mn = fmaxf(mo, tmax);
            float f  = __expf(mo - mn);
            rz[tid] = rz[tid] * f + tz * __expf(tmax - mn);
            rm[tid] = mn; fr[tid] = f; mnw[tid] = mn;
            g_mt[(bh * 8 + t) * Ls + i0 + tid] = mn;
        }
        __syncthreads();

        // u = exp(s - m_new): store fp16 to SMEM (Ws) and GMEM (g_w)
        #pragma unroll
        for (int i = 0; i < 4; i++) {
            int r0 = wm * 64 + i * 16 + g;
            int r1 = r0 + 8;
            float mn0 = mnw[r0], mn1 = mnw[r1];
            #pragma unroll
            for (int j = 0; j < 4; j++) {
                float u0 = __expf(c[i][j][0] - mn0);
                float u1 = __expf(c[i][j][1] - mn0);
                float u2 = __expf(c[i][j][2] - mn1);
                float u3 = __expf(c[i][j][3] - mn1);
                __half2 h01 = __floats2half2_rn(u0, u1);
                __half2 h23 = __floats2half2_rn(u2, u3);
                int cu = wn * 16 + j * 4 + t4;
                Ws2[r0 * 68 + cu] = h01;
                Ws2[r1 * 68 + cu] = h23;
                int col = j0 + wn * 32 + j * 8 + 2 * t4;
                *(__half2*)&g_w[(size_t)bh * LL + (size_t)(i0 + r0) * Ls + col] = h01;
                *(__half2*)&g_w[(size_t)bh * LL + (size_t)(i0 + r1) * Ls + col] = h23;
            }
        }

        // rescale ctx accumulator
        #pragma unroll
        for (int i = 0; i < 4; i++) {
            int r0 = wm * 64 + i * 16 + g;
            float f0 = fr[r0], f1 = fr[r0 + 8];
            #pragma unroll
            for (int j = 0; j < 2; j++) {
                ctx[i][j][0] *= f0; ctx[i][j][1] *= f0;
                ctx[i][j][2] *= f1; ctx[i][j][3] *= f1;
            }
        }

        // V tile -> transposed fp16 Vt [d][j], row stride 136 halves
        #pragma unroll
        for (int it = 0; it < 8; it++) {
            int idx = tid + it * 256;
            int j = idx & 127, dg = idx >> 7;   // dg 0..15
            float4 v = *(const float4*)&g_v[((size_t)(j0 + j) * Bb + b) * Es + h * 64 + dg * 4];
            Vh[(dg * 4 + 0) * 136 + j] = __float2half_rn(v.x);
            Vh[(dg * 4 + 1) * 136 + j] = __float2half_rn(v.y);
            Vh[(dg * 4 + 2) * 136 + j] = __float2half_rn(v.z);
            Vh[(dg * 4 + 3) * 136 + j] = __float2half_rn(v.w);
        }
        __syncthreads();

        // PV: m16n8k16 fp16 MMA, 8 k-steps of 16
        #pragma unroll
        for (int k2 = 0; k2 < 8; k2++) {
            int ku = k2 * 8;                     // half2 unit offset
            uint32_t a[4][4], b2[2][2];
            #pragma unroll
            for (int i = 0; i < 4; i++) {
                int m = wm * 64 + i * 16;
                a[i][0] = *(const uint32_t*)&Ws2[(m + g) * 68 + ku + t4];
                a[i][1] = *(const uint32_t*)&Ws2[(m + g + 8) * 68 + ku + t4];
                a[i][2] = *(const uint32_t*)&Ws2[(m + g) * 68 + ku + 4 + t4];
                a[i][3] = *(const uint32_t*)&Ws2[(m + g + 8) * 68 + ku + 4 + t4];
            }
            #pragma unroll
            for (int j = 0; j < 2; j++) {
                int n = wn * 16 + j * 8;
                b2[j][0] = *(const uint32_t*)&Vt2[(n + g) * 68 + ku + t4];
                b2[j][1] = *(const uint32_t*)&Vt2[(n + g) * 68 + ku + 4 + t4];
            }
            #pragma unroll
            for (int i = 0; i < 4; i++)
                #pragma unroll
                for (int j = 0; j < 2; j++)
                    mma_f16(ctx[i][j], a[i], b2[j]);
        }
        __syncthreads();
    }

    if (tid < 128) {
        float2 st = { rm[tid], 1.0f / rz[tid] };
        g_stats[bh * Ls + i0 + tid] = st;
    }

    // ctx writeout, normalized by 1/Z
    #pragma unroll
    for (int i = 0; i < 4; i++) {
        int r0 = wm * 64 + i * 16 + g, r1 = r0 + 8;
        float iz0 = 1.0f / rz[r0], iz1 = 1.0f / rz[r1];
        #pragma unroll
        for (int j = 0; j < 2; j++) {
            int d = wn * 16 + j * 8 + 2 * t4;
            float2 v0 = { ctx[i][j][0] * iz0, ctx[i][j][1] * iz0 };
            float2 v1 = { ctx[i][j][2] * iz1, ctx[i][j][3] * iz1 };
            *(float2*)&g_ctx[((size_t)(i0 + r0) * Bb + b) * Es + h * 64 + d] = v0;
            *(float2*)&g_ctx[((size_t)(i0 + r1) * Bb + b) * Es + h * 64 + d] = v1;
        }
    }
}

// ---------------------------------------------------------------------------
// fac[bh][t][i] = exp(m_used - m_fin) * invZ
// ---------------------------------------------------------------------------
__global__ __launch_bounds__(256) void fac_kernel()
{
    int idx = blockIdx.x * 256 + threadIdx.x;     // < BH*8*1024
    int bh = idx >> 13;
    int i  = idx & 1023;
    float2 st = g_stats[bh * Ls + i];
    g_fac[idx] = __expf(g_mt[idx] - st.x) * st.y;
}

// ---------------------------------------------------------------------------
// avg_weights[b,i,j] = (1/H) * sum_h u[bh,i,j] * fac[bh, j>>7, i]
// ---------------------------------------------------------------------------
__global__ __launch_bounds__(256) void avg_kernel(float* __restrict__ out2)
{
    int idx = blockIdx.x * 256 + threadIdx.x;      // < 1M float4 units
    int b = idx >> 18;
    int rem = idx & 262143;
    int i = rem >> 8;
    int j = (rem & 255) * 4;
    int t = j >> 7;
    float4 acc = { 0.f, 0.f, 0.f, 0.f };
    #pragma unroll
    for (int h = 0; h < Hs; h++) {
        int bh = b * Hs + h;
        const __half2* wp = (const __half2*)&g_w[(size_t)bh * LL + (size_t)i * Ls + j];
        __half2 w0 = wp[0], w1 = wp[1];
        float fac = g_fac[(bh * 8 + t) * Ls + i];
        float2 f0 = __half22float2(w0), f1 = __half22float2(w1);
        acc.x += f0.x * fac;
        acc.y += f0.y * fac;
        acc.z += f1.x * fac;
        acc.w += f1.y * fac;
    }
    const float sc = 1.0f / Hs;
    acc.x *= sc; acc.y *= sc; acc.z *= sc; acc.w *= sc;
    *(float4*)&out2[(size_t)idx * 4] = acc;
}

// ---------------------------------------------------------------------------
extern "C" void kernel_launch(void* const* d_in, const int* in_sizes, int n_in,
                              void* d_out, int out_size)
{
    const float* query = (const float*)d_in[0];
    const float* key   = (const float*)d_in[1];
    const float* value = (const float*)d_in[2];
    const float* mask  = (const float*)d_in[3];
    const float* w_in  = (const float*)d_in[4];
    const float* b_in  = (const float*)d_in[5];
    const float* w_out = (const float*)d_in[6];
    const float* b_out = (const float*)d_in[7];
    float* out  = (float*)d_out;                  // attn_output [L,B,E]
    float* out2 = out + (size_t)LB * Es;          // avg_weights [B,L,L]

    float *pq, *pk, *pv, *pctx;
    cudaGetSymbolAddress((void**)&pq,   g_q);
    cudaGetSymbolAddress((void**)&pk,   g_k);
    cudaGetSymbolAddress((void**)&pv,   g_v);
    cudaGetSymbolAddress((void**)&pctx, g_ctx);

    cudaFuncSetAttribute(flash_attn, cudaFuncAttributeMaxDynamicSharedMemorySize, FL_SMEM);

    dim3 gproj(Es / 128, LB / 128);                // (8, 32)

    gemm_nt_tc<<<gproj, 256>>>(query, w_in,               b_in,          pq);
    gemm_nt_tc<<<gproj, 256>>>(key,   w_in + Es * Es,     b_in + Es,     pk);
    gemm_nt_tc<<<gproj, 256>>>(value, w_in + 2 * Es * Es, b_in + 2 * Es, pv);

    flash_attn<<<dim3(8, BH), 256, FL_SMEM>>>(mask);
    fac_kernel<<<(BH * 8 * Ls) / 256, 256>>>();
    avg_kernel<<<(Bb * LL / 4) / 256, 256>>>(out2);

    gemm_nt_tc<<<gproj, 256>>>(pctx, w_out, b_out, out);
}

// round 10
// speedup vs baseline: 1.3166x; 1.3166x over previous
#include <cuda_runtime.h>
#include <cuda_fp16.h>
#include <cstdint>
#include <math_constants.h>

#define Ls 1024
#define Bb 4
#define Es 1024
#define Hs 16
#define LB (Ls*Bb)        // 4096
#define BH (Bb*Hs)        // 64
#define LL (Ls*Ls)        // 1048576

// Scratch (device globals — allocation-free)
__device__ __half g_qh[LB*Es];
__device__ __half g_kh[LB*Es];
__device__ __half g_vh[LB*Es];
__device__ float  g_ctx[LB*Es];
__device__ __half g_w[(size_t)BH*LL];      // 128 MB unnormalized weights u=exp(s-m_used)
__device__ float  g_mt[BH*8*Ls];           // m_used per (bh, j-tile, row)
__device__ float  g_fac[BH*8*Ls];          // exp(m_used - m_fin) * invZ
__device__ float2 g_stats[BH*Ls];          // per-row (m_fin, 1/Z)

// ---------------------------------------------------------------------------
__device__ __forceinline__ void mma_f16(float c[4], const uint32_t a[4], const uint32_t b[2]) {
    asm volatile(
        "mma.sync.aligned.m16n8k16.row.col.f32.f16.f16.f32 "
        "{%0,%1,%2,%3}, {%4,%5,%6,%7}, {%8,%9}, {%0,%1,%2,%3};\n"
        : "+f"(c[0]), "+f"(c[1]), "+f"(c[2]), "+f"(c[3])
        : "r"(a[0]), "r"(a[1]), "r"(a[2]), "r"(a[3]), "r"(b[0]), "r"(b[1]));
}

// ---------------------------------------------------------------------------
// NT GEMM, fp16 MMA: C[4096,1024] = A @ W^T + bias.  A,W fp32 in; smem fp16.
// 128x128 tile, BK=32, 8 warps (2x4), warp tile 64x32. OUTH: fp16 vs fp32 C.
// ---------------------------------------------------------------------------
template<int OUTH>
__global__ __launch_bounds__(256, 2) void gemm_nt_h(
    const float* __restrict__ A, const float* __restrict__ W,
    const float* __restrict__ bias, void* __restrict__ Cv)
{
    const int K = 1024, N = 1024;
    __shared__ __half2 As2[128 * 20];     // stride 20 half2 = 40 halves
    __shared__ __half2 Bs2[128 * 20];
    const int tid = threadIdx.x;
    const int lane = tid & 31, wid = tid >> 5;
    const int g = lane >> 2, t4 = lane & 3;
    const int wm = wid >> 2, wn = wid & 3;           // 2 x 4 warps
    const int row0 = blockIdx.y * 128, col0 = blockIdx.x * 128;

    float c[4][4][4] = {};
    const int lr = tid >> 3;
    const int lc = (tid & 7) * 4;

    for (int kb = 0; kb < K; kb += 32) {
        #pragma unroll
        for (int it = 0; it < 4; it++) {
            int r = lr + it * 32;
            float4 va = *(const float4*)&A[(size_t)(row0 + r) * K + kb + lc];
            As2[r * 20 + lc / 2]     = __floats2half2_rn(va.x, va.y);
            As2[r * 20 + lc / 2 + 1] = __floats2half2_rn(va.z, va.w);
            float4 vb = *(const float4*)&W[(size_t)(col0 + r) * K + kb + lc];
            Bs2[r * 20 + lc / 2]     = __floats2half2_rn(vb.x, vb.y);
            Bs2[r * 20 + lc / 2 + 1] = __floats2half2_rn(vb.z, vb.w);
        }
        __syncthreads();
        #pragma unroll
        for (int ks2 = 0; ks2 < 16; ks2 += 8) {       // two k-steps of 16 halves
            uint32_t a[4][4], b2[4][2];
            #pragma unroll
            for (int i = 0; i < 4; i++) {
                int m = wm * 64 + i * 16;
                a[i][0] = *(const uint32_t*)&As2[(m + g) * 20 + ks2 + t4];
                a[i][1] = *(const uint32_t*)&As2[(m + g + 8) * 20 + ks2 + t4];
                a[i][2] = *(const uint32_t*)&As2[(m + g) * 20 + ks2 + 4 + t4];
                a[i][3] = *(const uint32_t*)&As2[(m + g + 8) * 20 + ks2 + 4 + t4];
            }
            #pragma unroll
            for (int j = 0; j < 4; j++) {
                int n = wn * 32 + j * 8;
                b2[j][0] = *(const uint32_t*)&Bs2[(n + g) * 20 + ks2 + t4];
                b2[j][1] = *(const uint32_t*)&Bs2[(n + g) * 20 + ks2 + 4 + t4];
            }
            #pragma unroll
            for (int i = 0; i < 4; i++)
                #pragma unroll
                for (int j = 0; j < 4; j++)
                    mma_f16(c[i][j], a[i], b2[j]);
        }
        __syncthreads();
    }

    #pragma unroll
    for (int i = 0; i < 4; i++) {
        int r = row0 + wm * 64 + i * 16 + g;
        #pragma unroll
        for (int j = 0; j < 4; j++) {
            int cc = col0 + wn * 32 + j * 8 + 2 * t4;
            float2 bv = *(const float2*)&bias[cc];
            if (OUTH) {
                __half* C = (__half*)Cv;
                *(__half2*)&C[(size_t)r * N + cc] =
                    __floats2half2_rn(c[i][j][0] + bv.x, c[i][j][1] + bv.y);
                *(__half2*)&C[(size_t)(r + 8) * N + cc] =
                    __floats2half2_rn(c[i][j][2] + bv.x, c[i][j][3] + bv.y);
            } else {
                float* C = (float*)Cv;
                float2 v0 = { c[i][j][0] + bv.x, c[i][j][1] + bv.y };
                float2 v1 = { c[i][j][2] + bv.x, c[i][j][3] + bv.y };
                *(float2*)&C[(size_t)r * N + cc] = v0;
                *(float2*)&C[(size_t)(r + 8) * N + cc] = v1;
            }
        }
    }
}

// ---------------------------------------------------------------------------
// flash_attn v2: fp16 q/k/v, fp16 QK + PV MMA, register prefetch of next K/V.
// Per (bh, 128-row i-tile): sweep 8 j-tiles; online softmax; u fp16 -> g_w.
// SMEM (bytes): Qh[128][72]h @0 (18432), Kh[128][72]h @18432 (18432),
//   Ws[128][136]h @36864 (34816), Vt[64][136]h @71680 (17408),
//   pm @89088 (2048), pz @91136 (2048), rm @93184, rz @93696, fr @94208,
//   mnw @94720  -> total 95232
// ---------------------------------------------------------------------------
#define FL_SMEM 95232
__global__ __launch_bounds__(256, 1) void flash_attn(const float* __restrict__ mask)
{
    extern __shared__ char smraw[];
    __half2* Qh2 = (__half2*)smraw;                 // stride 36 half2
    __half2* Kh2 = (__half2*)(smraw + 18432);       // stride 36
    __half2* Ws2 = (__half2*)(smraw + 36864);       // stride 68
    __half*  Vh  = (__half*)(smraw + 71680);        // stride 136 halves
    __half2* Vt2 = (__half2*)(smraw + 71680);       // stride 68
    float* pm  = (float*)(smraw + 89088);
    float* pz  = (float*)(smraw + 91136);
    float* rm  = (float*)(smraw + 93184);
    float* rz  = (float*)(smraw + 93696);
    float* fr  = (float*)(smraw + 94208);
    float* mnw = (float*)(smraw + 94720);

    const int bh = blockIdx.y;
    const int b = bh >> 4, h = bh & 15;
    const int i0 = blockIdx.x * 128;
    const int tid = threadIdx.x;
    const int lane = tid & 31, wid = tid >> 5;
    const int g = lane >> 2, t4 = lane & 3;
    const int wm = wid >> 2, wn = wid & 3;          // 2 x 4 warps

    if (tid < 128) { rm[tid] = -CUDART_INF_F; rz[tid] = 0.f; }

    const int krow = tid >> 3, kc8 = tid & 7;       // K/Q copy indexing

    // Q tile [128 x 64] fp16
    #pragma unroll
    for (int it = 0; it < 4; it++) {
        int r = krow + it * 32;
        *(uint4*)&Qh2[r * 36 + kc8 * 4] =
            *(const uint4*)&g_qh[((size_t)(i0 + r) * Bb + b) * Es + h * 64 + kc8 * 8];
    }
    // K tile j0=0
    #pragma unroll
    for (int it = 0; it < 4; it++) {
        int r = krow + it * 32;
        *(uint4*)&Kh2[r * 36 + kc8 * 4] =
            *(const uint4*)&g_kh[((size_t)r * Bb + b) * Es + h * 64 + kc8 * 8];
    }
    // V tile j0=0 (transposed into Vt)
    #pragma unroll
    for (int it = 0; it < 8; it++) {
        int idx = tid + it * 256;
        int j = idx & 127, dg = idx >> 7;           // dg 0..15 (4 halves each)
        uint2 v = *(const uint2*)&g_vh[((size_t)j * Bb + b) * Es + h * 64 + dg * 4];
        __half2 p0 = *(__half2*)&v.x, p1 = *(__half2*)&v.y;
        Vh[(dg * 4 + 0) * 136 + j] = __low2half(p0);
        Vh[(dg * 4 + 1) * 136 + j] = __high2half(p0);
        Vh[(dg * 4 + 2) * 136 + j] = __low2half(p1);
        Vh[(dg * 4 + 3) * 136 + j] = __high2half(p1);
    }
    __syncthreads();

    float ctx[4][2][4] = {};
    const float* Mp = mask + (size_t)b * LL;

    for (int t = 0; t < 8; t++) {
        const int j0 = t * 128;

        // prefetch next K/V tiles into registers (hidden behind this tile's math)
        uint4 kp[4];
        uint2 vp[8];
        const bool pref = (t < 7);
        if (pref) {
            const int j0n = j0 + 128;
            #pragma unroll
            for (int it = 0; it < 4; it++) {
                int r = krow + it * 32;
                kp[it] = *(const uint4*)&g_kh[((size_t)(j0n + r) * Bb + b) * Es + h * 64 + kc8 * 8];
            }
            #pragma unroll
            for (int it = 0; it < 8; it++) {
                int idx = tid + it * 256;
                int j = idx & 127, dg = idx >> 7;
                vp[it] = *(const uint2*)&g_vh[((size_t)(j0n + j) * Bb + b) * Es + h * 64 + dg * 4];
            }
        }

        // QK MMA (fp16, K=64 -> 4 k-steps of 16)
        float c[4][4][4] = {};
        #pragma unroll
        for (int ks2 = 0; ks2 < 32; ks2 += 8) {
            uint32_t a[4][4], b2[4][2];
            #pragma unroll
            for (int i = 0; i < 4; i++) {
                int m = wm * 64 + i * 16;
                a[i][0] = *(const uint32_t*)&Qh2[(m + g) * 36 + ks2 + t4];
                a[i][1] = *(const uint32_t*)&Qh2[(m + g + 8) * 36 + ks2 + t4];
                a[i][2] = *(const uint32_t*)&Qh2[(m + g) * 36 + ks2 + 4 + t4];
                a[i][3] = *(const uint32_t*)&Qh2[(m + g + 8) * 36 + ks2 + 4 + t4];
            }
            #pragma unroll
            for (int j = 0; j < 4; j++) {
                int n = wn * 32 + j * 8;
                b2[j][0] = *(const uint32_t*)&Kh2[(n + g) * 36 + ks2 + t4];
                b2[j][1] = *(const uint32_t*)&Kh2[(n + g) * 36 + ks2 + 4 + t4];
            }
            #pragma unroll
            for (int i = 0; i < 4; i++)
                #pragma unroll
                for (int j = 0; j < 4; j++)
                    mma_f16(c[i][j], a[i], b2[j]);
        }

        // mask + scale
        #pragma unroll
        for (int i = 0; i < 4; i++) {
            int r = i0 + wm * 64 + i * 16 + g;
            #pragma unroll
            for (int j = 0; j < 4; j++) {
                int cc = j0 + wn * 32 + j * 8 + 2 * t4;
                float2 m0 = *(const float2*)&Mp[(size_t)r * Ls + cc];
                float2 m1 = *(const float2*)&Mp[(size_t)(r + 8) * Ls + cc];
                c[i][j][0] = c[i][j][0] * 0.125f + m0.x;
                c[i][j][1] = c[i][j][1] * 0.125f + m0.y;
                c[i][j][2] = c[i][j][2] * 0.125f + m1.x;
                c[i][j][3] = c[i][j][3] * 0.125f + m1.y;
            }
        }

        // tile-local stats per row -> pm/pz
        #pragma unroll
        for (int i = 0; i < 4; i++) {
            #pragma unroll
            for (int sub = 0; sub < 2; sub++) {
                float tm = c[i][0][2 * sub];
                #pragma unroll
                for (int j = 0; j < 4; j++) {
                    tm = fmaxf(tm, c[i][j][2 * sub + 0]);
                    tm = fmaxf(tm, c[i][j][2 * sub + 1]);
                }
                float ts = 0.f;
                #pragma unroll
                for (int j = 0; j < 4; j++) {
                    ts += __expf(c[i][j][2 * sub + 0] - tm);
                    ts += __expf(c[i][j][2 * sub + 1] - tm);
                }
                #pragma unroll
                for (int o = 1; o < 4; o <<= 1) {
                    float om = __shfl_xor_sync(0xffffffffu, tm, o);
                    float os = __shfl_xor_sync(0xffffffffu, ts, o);
                    float nm = fmaxf(tm, om);
                    ts = ts * __expf(tm - nm) + os * __expf(om - nm);
                    tm = nm;
                }
                if (t4 == 0) {
                    int rr = wm * 64 + i * 16 + g + 8 * sub;
                    pm[wn * 128 + rr] = tm;
                    pz[wn * 128 + rr] = ts;
                }
            }
        }
        __syncthreads();

        // merge across warps + online update
        if (tid < 128) {
            float tmax = pm[tid];
            #pragma unroll
            for (int w = 1; w < 4; w++) tmax = fmaxf(tmax, pm[w * 128 + tid]);
            float tz = 0.f;
            #pragma unroll
            for (int w = 0; w < 4; w++)
                tz += pz[w * 128 + tid] * __expf(pm[w * 128 + tid] - tmax);
            float mo = rm[tid];
            float mn = fmaxf(mo, tmax);
            float f  = __expf(mo - mn);
            rz[tid] = rz[tid] * f + tz * __expf(tmax - mn);
            rm[tid] = mn; fr[tid] = f; mnw[tid] = mn;
            g_mt[(bh * 8 + t) * Ls + i0 + tid] = mn;
        }
        __syncthreads();

        // u = exp(s - m_new): fp16 to SMEM (Ws) + GMEM (g_w)
        #pragma unroll
        for (int i = 0; i < 4; i++) {
            int r0 = wm * 64 + i * 16 + g;
            int r1 = r0 + 8;
            float mn0 = mnw[r0], mn1 = mnw[r1];
            #pragma unroll
            for (int j = 0; j < 4; j++) {
                float u0 = __expf(c[i][j][0] - mn0);
                float u1 = __expf(c[i][j][1] - mn0);
                float u2 = __expf(c[i][j][2] - mn1);
                float u3 = __expf(c[i][j][3] - mn1);
                __half2 h01 = __floats2half2_rn(u0, u1);
                __half2 h23 = __floats2half2_rn(u2, u3);
                int cu = wn * 16 + j * 4 + t4;
                Ws2[r0 * 68 + cu] = h01;
                Ws2[r1 * 68 + cu] = h23;
                int col = j0 + wn * 32 + j * 8 + 2 * t4;
                *(__half2*)&g_w[(size_t)bh * LL + (size_t)(i0 + r0) * Ls + col] = h01;
                *(__half2*)&g_w[(size_t)bh * LL + (size_t)(i0 + r1) * Ls + col] = h23;
            }
        }

        // rescale ctx accumulator
        #pragma unroll
        for (int i = 0; i < 4; i++) {
            int r0 = wm * 64 + i * 16 + g;
            float f0 = fr[r0], f1 = fr[r0 + 8];
            #pragma unroll
            for (int j = 0; j < 2; j++) {
                ctx[i][j][0] *= f0; ctx[i][j][1] *= f0;
                ctx[i][j][2] *= f1; ctx[i][j][3] *= f1;
            }
        }
        __syncthreads();   // Ws visible to all warps

        // PV: m16n8k16 fp16 MMA, 8 k-steps of 16
        #pragma unroll
        for (int k2 = 0; k2 < 8; k2++) {
            int ku = k2 * 8;
            uint32_t a[4][4], b2[2][2];
            #pragma unroll
            for (int i = 0; i < 4; i++) {
                int m = wm * 64 + i * 16;
                a[i][0] = *(const uint32_t*)&Ws2[(m + g) * 68 + ku + t4];
                a[i][1] = *(const uint32_t*)&Ws2[(m + g + 8) * 68 + ku + t4];
                a[i][2] = *(const uint32_t*)&Ws2[(m + g) * 68 + ku + 4 + t4];
                a[i][3] = *(const uint32_t*)&Ws2[(m + g + 8) * 68 + ku + 4 + t4];
            }
            #pragma unroll
            for (int j = 0; j < 2; j++) {
                int n = wn * 16 + j * 8;
                b2[j][0] = *(const uint32_t*)&Vt2[(n + g) * 68 + ku + t4];
                b2[j][1] = *(const uint32_t*)&Vt2[(n + g) * 68 + ku + 4 + t4];
            }
            #pragma unroll
            for (int i = 0; i < 4; i++)
                #pragma unroll
                for (int j = 0; j < 2; j++)
                    mma_f16(ctx[i][j], a[i], b2[j]);
        }
        __syncthreads();   // done reading Kh/Vt/Ws this iteration

        // commit prefetched K/V for next tile
        if (pref) {
            #pragma unroll
            for (int it = 0; it < 4; it++) {
                int r = krow + it * 32;
                *(uint4*)&Kh2[r * 36 + kc8 * 4] = kp[it];
            }
            #pragma unroll
            for (int it = 0; it < 8; it++) {
                int idx = tid + it * 256;
                int j = idx & 127, dg = idx >> 7;
                __half2 p0 = *(__half2*)&vp[it].x, p1 = *(__half2*)&vp[it].y;
                Vh[(dg * 4 + 0) * 136 + j] = __low2half(p0);
                Vh[(dg * 4 + 1) * 136 + j] = __high2half(p0);
                Vh[(dg * 4 + 2) * 136 + j] = __low2half(p1);
                Vh[(dg * 4 + 3) * 136 + j] = __high2half(p1);
            }
            __syncthreads();
        }
    }

    if (tid < 128) {
        float2 st = { rm[tid], 1.0f / rz[tid] };
        g_stats[bh * Ls + i0 + tid] = st;
    }

    // ctx writeout, normalized by 1/Z
    #pragma unroll
    for (int i = 0; i < 4; i++) {
        int r0 = wm * 64 + i * 16 + g, r1 = r0 + 8;
        float iz0 = 1.0f / rz[r0], iz1 = 1.0f / rz[r1];
        #pragma unroll
        for (int j = 0; j < 2; j++) {
            int d = wn * 16 + j * 8 + 2 * t4;
            float2 v0 = { ctx[i][j][0] * iz0, ctx[i][j][1] * iz0 };
            float2 v1 = { ctx[i][j][2] * iz1, ctx[i][j][3] * iz1 };
            *(float2*)&g_ctx[((size_t)(i0 + r0) * Bb + b) * Es + h * 64 + d] = v0;
            *(float2*)&g_ctx[((size_t)(i0 + r1) * Bb + b) * Es + h * 64 + d] = v1;
        }
    }
}

// ---------------------------------------------------------------------------
// fac[bh][t][i] = exp(m_used - m_fin) * invZ
// ---------------------------------------------------------------------------
__global__ __launch_bounds__(256) void fac_kernel()
{
    int idx = blockIdx.x * 256 + threadIdx.x;     // < BH*8*1024
    int bh = idx >> 13;
    int i  = idx & 1023;
    float2 st = g_stats[bh * Ls + i];
    g_fac[idx] = __expf(g_mt[idx] - st.x) * st.y;
}

// ---------------------------------------------------------------------------
// avg_weights[b,i,j] = (1/H) * sum_h u[bh,i,j] * fac[bh, j>>7, i]
// ---------------------------------------------------------------------------
__global__ __launch_bounds__(256) void avg_kernel(float* __restrict__ out2)
{
    int idx = blockIdx.x * 256 + threadIdx.x;      // < 1M float4 units
    int b = idx >> 18;
    int rem = idx & 262143;
    int i = rem >> 8;
    int j = (rem & 255) * 4;
    int t = j >> 7;
    float4 acc = { 0.f, 0.f, 0.f, 0.f };
    #pragma unroll
    for (int h = 0; h < Hs; h++) {
        int bh = b * Hs + h;
        const __half2* wp = (const __half2*)&g_w[(size_t)bh * LL + (size_t)i * Ls + j];
        __half2 w0 = wp[0], w1 = wp[1];
        float fac = g_fac[(bh * 8 + t) * Ls + i];
        float2 f0 = __half22float2(w0), f1 = __half22float2(w1);
        acc.x += f0.x * fac;
        acc.y += f0.y * fac;
        acc.z += f1.x * fac;
        acc.w += f1.y * fac;
    }
    const float sc = 1.0f / Hs;
    acc.x *= sc; acc.y *= sc; acc.z *= sc; acc.w *= sc;
    *(float4*)&out2[(size_t)idx * 4] = acc;
}

// ---------------------------------------------------------------------------
extern "C" void kernel_launch(void* const* d_in, const int* in_sizes, int n_in,
                              void* d_out, int out_size)
{
    const float* query = (const float*)d_in[0];
    const float* key   = (const float*)d_in[1];
    const float* value = (const float*)d_in[2];
    const float* mask  = (const float*)d_in[3];
    const float* w_in  = (const float*)d_in[4];
    const float* b_in  = (const float*)d_in[5];
    const float* w_out = (const float*)d_in[6];
    const float* b_out = (const float*)d_in[7];
    float* out  = (float*)d_out;                  // attn_output [L,B,E]
    float* out2 = out + (size_t)LB * Es;          // avg_weights [B,L,L]

    __half *pqh, *pkh, *pvh;
    float *pctx;
    cudaGetSymbolAddress((void**)&pqh,  g_qh);
    cudaGetSymbolAddress((void**)&pkh,  g_kh);
    cudaGetSymbolAddress((void**)&pvh,  g_vh);
    cudaGetSymbolAddress((void**)&pctx, g_ctx);

    cudaFuncSetAttribute(flash_attn, cudaFuncAttributeMaxDynamicSharedMemorySize, FL_SMEM);

    dim3 gproj(Es / 128, LB / 128);                // (8, 32)

    gemm_nt_h<1><<<gproj, 256>>>(query, w_in,               b_in,          (void*)pqh);
    gemm_nt_h<1><<<gproj, 256>>>(key,   w_in + Es * Es,     b_in + Es,     (void*)pkh);
    gemm_nt_h<1><<<gproj, 256>>>(value, w_in + 2 * Es * Es, b_in + 2 * Es, (void*)pvh);

    flash_attn<<<dim3(8, BH), 256, FL_SMEM>>>(mask);
    fac_kernel<<<(BH * 8 * Ls) / 256, 256>>>();
    avg_kernel<<<(Bb * LL / 4) / 256, 256>>>(out2);

    gemm_nt_h<0><<<gproj, 256>>>(pctx, w_out, b_out, out);
}